// round 13
// baseline (speedup 1.0000x reference)
#include <cuda_runtime.h>

#define N 256
#define NPH (N/2 + 2)          // 130 phase layers
#define NSTAGES (N/2)          // 128 stages; stages 1..127 followed by crossing

// Precomputed exp(i*theta) for all layers: [130][256] complex interleaved.
__device__ float2 g_phases[NPH * N];

__global__ void phase_kernel(const float* __restrict__ thetas, int n) {
    int i = blockIdx.x * blockDim.x + threadIdx.x;
    if (i < n) {
        float s, c;
        sincosf(thetas[i], &s, &c);
        g_phases[i] = make_float2(c, s);
    }
}

// One WARP per column; EIGHT warps per CTA so each SMSP hosts 2 warps whose
// dependency stalls interleave. Lane l owns rows 8l..8l+7 as 4 complex pairs
// (X[j],Y[j]) in registers. MMI/phase/MMI are pair-local; the crossing has 3
// lane-internal couplings plus one complex shuffle exchange per side. Phases
// stream through a 4-deep register prefetch ring (16 LDG.128 in flight/warp).
// Output: REAL PART only, row-major float32 [N][N].
__global__ __launch_bounds__(256) void mesh_kernel(float* __restrict__ out) {
    const int lane = threadIdx.x & 31;
    const int col  = blockIdx.x * 8 + (threadIdx.x >> 5);

    const float AT = sqrtf(0.98f * 0.505f);
    const float AR = sqrtf(0.98f * 0.495f);
    const float CS   = sqrtf(0.98f * 0.01f);
    const float CN   = sqrtf(0.98f * 0.99f);
    const float THRU = CN;                    // pass-through rows 0, N-1

    // Initial state: column col of diag(exp(i*theta[0]))
    float2 X[4], Y[4];
    #pragma unroll
    for (int j = 0; j < 4; j++) { X[j] = make_float2(0.f, 0.f); Y[j] = make_float2(0.f, 0.f); }
    if ((col >> 3) == lane) {
        float2 p = g_phases[col];
        int j = (col >> 1) & 3;
        if (col & 1) Y[j] = p; else X[j] = p;
    }

    // Phase table as float4: one float4 = phases of rows (2m,2m+1).
    // Layer s, pair j of this lane -> phb[s*128 + j].
    const float4* __restrict__ phb = reinterpret_cast<const float4*>(g_phases) + 4 * lane;

    // 4-slot prefetch ring: before stage s executes, slots hold layers
    // s, s+1, s+2, s+3 (clamped to 129 = final diag layer).
    float4 P0[4], P1[4], P2[4], P3[4];

#define LOADPH(PH, layer) do {                                              \
        int _ly = (layer) <= (NPH - 1) ? (layer) : (NPH - 1);               \
        _Pragma("unroll")                                                   \
        for (int j = 0; j < 4; j++) PH[j] = phb[_ly * 128 + j];             \
    } while (0)

    LOADPH(P0, 1);
    LOADPH(P1, 2);
    LOADPH(P2, 3);
    LOADPH(P3, 4);

    // One mesh stage using phase slot PH (holds layer SCUR); refills PH with
    // layer SCUR+4 right after its last use so 16 loads stay in flight.
#define STEP(SCUR, PH) do {                                                 \
        _Pragma("unroll")                                                   \
        for (int j = 0; j < 4; j++) {                                       \
            float2 x = X[j], y = Y[j];                                      \
            float4 p = PH[j];                                               \
            float x1r = AT * x.x - AR * y.y;                                \
            float x1i = AT * x.y + AR * y.x;                                \
            float y1r = AT * y.x - AR * x.y;                                \
            float y1i = AT * y.y + AR * x.x;                                \
            float x2r = p.x * x1r - p.y * x1i;                              \
            float x2i = p.x * x1i + p.y * x1r;                              \
            float y2r = p.z * y1r - p.w * y1i;                              \
            float y2i = p.z * y1i + p.w * y1r;                              \
            X[j].x = AT * x2r - AR * y2i;                                   \
            X[j].y = AT * x2i + AR * y2r;                                   \
            Y[j].x = AT * y2r - AR * x2i;                                   \
            Y[j].y = AT * y2i + AR * x2r;                                   \
        }                                                                   \
        LOADPH(PH, (SCUR) + 4);                                             \
        if ((SCUR) < NSTAGES) {                                             \
            float xnr = __shfl_down_sync(0xFFFFFFFFu, X[0].x, 1);           \
            float xni = __shfl_down_sync(0xFFFFFFFFu, X[0].y, 1);           \
            float ypr = __shfl_up_sync  (0xFFFFFFFFu, Y[3].x, 1);           \
            float ypi = __shfl_up_sync  (0xFFFFFFFFu, Y[3].y, 1);           \
            float2 nx0, ny3;                                                \
            _Pragma("unroll")                                               \
            for (int j = 0; j < 3; j++) {                                   \
                float2 yj = Y[j], xj1 = X[j+1];                             \
                Y[j].x   = CS * yj.x  - CN * xj1.y;                         \
                Y[j].y   = CS * yj.y  + CN * xj1.x;                         \
                X[j+1].x = CS * xj1.x - CN * yj.y;                          \
                X[j+1].y = CS * xj1.y + CN * yj.x;                          \
            }                                                               \
            if (lane < 31) {                                                \
                ny3.x = CS * Y[3].x - CN * xni;                             \
                ny3.y = CS * Y[3].y + CN * xnr;                             \
            } else {                                                        \
                ny3.x = THRU * Y[3].x;                                      \
                ny3.y = THRU * Y[3].y;                                      \
            }                                                               \
            if (lane > 0) {                                                 \
                nx0.x = CS * X[0].x - CN * ypi;                             \
                nx0.y = CS * X[0].y + CN * ypr;                             \
            } else {                                                        \
                nx0.x = THRU * X[0].x;                                      \
                nx0.y = THRU * X[0].y;                                      \
            }                                                               \
            X[0] = nx0; Y[3] = ny3;                                         \
        }                                                                   \
    } while (0)

    #pragma unroll 1
    for (int s = 1; s <= NSTAGES; s += 4) {
        STEP(s + 0, P0);
        STEP(s + 1, P1);
        STEP(s + 2, P2);
        STEP(s + 3, P3);
    }

    // After s=125 refilled P0 with layer 129 (final diag), epilogue uses P0.
    // Store REAL PART only, row-major [N][N].
    #pragma unroll
    for (int j = 0; j < 4; j++) {
        float4 p = P0[j];
        float xr = p.x * X[j].x - p.y * X[j].y;   // Re(p0 * x)
        float yr = p.z * Y[j].x - p.w * Y[j].y;   // Re(p1 * y)
        int r0 = 8 * lane + 2 * j;
        out[r0 * N + col]       = xr;
        out[(r0 + 1) * N + col] = yr;
    }
}

extern "C" void kernel_launch(void* const* d_in, const int* in_sizes, int n_in,
                              void* d_out, int out_size) {
    const float* thetas = (const float*)d_in[0];
    int n = in_sizes[0];  // 130 * 256 = 33280

    phase_kernel<<<(n + 255) / 256, 256>>>(thetas, n);
    // 32 CTAs x 256 threads = 256 warps; 8 warps/CTA -> 2 warps per SMSP.
    mesh_kernel<<<N / 8, 256>>>((float*)d_out);
}

// round 14
// speedup vs baseline: 1.2088x; 1.2088x over previous
#include <cuda_runtime.h>

#define N 256
#define NPH (N/2 + 2)          // 130 phase layers
#define NSTAGES (N/2)          // 128 stages; stages 1..127 followed by crossing

// Precomputed exp(i*theta) for all layers: [130][256] complex interleaved.
__device__ float2 g_phases[NPH * N];

__global__ void phase_kernel(const float* __restrict__ thetas, int n) {
    int i = blockIdx.x * blockDim.x + threadIdx.x;
    if (i < n) {
        float s, c;
        sincosf(thetas[i], &s, &c);
        g_phases[i] = make_float2(c, s);
    }
}

// TWO warps per column (half-columns of 128 rows each), two columns per CTA:
// 4 warps/CTA -> one warp per SMSP, 128 CTAs -> one CTA per SM, 512 warps.
// Lane l of the half-h warp owns rows 128h+4l..128h+4l+3 as 2 complex pairs.
// MMI/phase/MMI are pair-local; the crossing has 1 lane-internal coupling,
// one shuffle exchange per side, and ONE inter-warp complex exchange
// (row 127<->128) via ping-pong smem + __syncthreads.
// Phases stream through a 4-deep register prefetch ring.
// Output: REAL PART only, row-major float32 [N][N].
__global__ __launch_bounds__(128) void mesh_kernel(float* __restrict__ out) {
    const int tid    = threadIdx.x;
    const int lane   = tid & 31;
    const int w      = tid >> 5;      // 0..3
    const int half   = w & 1;         // 0: rows 0-127, 1: rows 128-255
    const int colIdx = w >> 1;        // 0,1 within CTA
    const int col    = blockIdx.x * 2 + colIdx;

    const float AT = sqrtf(0.98f * 0.505f);
    const float AR = sqrtf(0.98f * 0.495f);
    const float CS   = sqrtf(0.98f * 0.01f);
    const float CN   = sqrtf(0.98f * 0.99f);
    const float THRU = CN;                    // pass-through rows 0, N-1

    // Ping-pong inter-warp exchange: [parity][colIdx]
    __shared__ float2 sAy[2][2];   // Y of row 127 (from half 0, lane 31)
    __shared__ float2 sBx[2][2];   // X of row 128 (from half 1, lane 0)

    // Initial state: column col of diag(exp(i*theta[0]))
    float2 X[2], Y[2];
    X[0] = make_float2(0.f, 0.f); X[1] = make_float2(0.f, 0.f);
    Y[0] = make_float2(0.f, 0.f); Y[1] = make_float2(0.f, 0.f);
    {
        int r = col & 127;
        if (half == (col >> 7) && lane == (r >> 2)) {
            float2 p = g_phases[col];
            int j = (r >> 1) & 1;
            if (col & 1) Y[j] = p; else X[j] = p;
        }
    }

    // Phase table as float4: one float4 = phases of rows (2m,2m+1).
    // Pair m = 64*half + 2*lane + j; layer s -> phb[s*128 + j].
    const float4* __restrict__ phb =
        reinterpret_cast<const float4*>(g_phases) + 64 * half + 2 * lane;

    // 4-slot prefetch ring: slots hold layers s..s+3 (clamped to 129).
    float4 P0[2], P1[2], P2[2], P3[2];

#define LOADPH(PH, layer) do {                                              \
        int _ly = (layer) <= (NPH - 1) ? (layer) : (NPH - 1);               \
        PH[0] = phb[_ly * 128 + 0];                                         \
        PH[1] = phb[_ly * 128 + 1];                                         \
    } while (0)

    LOADPH(P0, 1);
    LOADPH(P1, 2);
    LOADPH(P2, 3);
    LOADPH(P3, 4);

#define STEP(SCUR, PH) do {                                                 \
        _Pragma("unroll")                                                   \
        for (int j = 0; j < 2; j++) {                                       \
            float2 x = X[j], y = Y[j];                                      \
            float4 p = PH[j];                                               \
            float x1r = AT * x.x - AR * y.y;                                \
            float x1i = AT * x.y + AR * y.x;                                \
            float y1r = AT * y.x - AR * x.y;                                \
            float y1i = AT * y.y + AR * x.x;                                \
            float x2r = p.x * x1r - p.y * x1i;                              \
            float x2i = p.x * x1i + p.y * x1r;                              \
            float y2r = p.z * y1r - p.w * y1i;                              \
            float y2i = p.z * y1i + p.w * y1r;                              \
            X[j].x = AT * x2r - AR * y2i;                                   \
            X[j].y = AT * x2i + AR * y2r;                                   \
            Y[j].x = AT * y2r - AR * x2i;                                   \
            Y[j].y = AT * y2i + AR * x2r;                                   \
        }                                                                   \
        LOADPH(PH, (SCUR) + 4);                                             \
        if ((SCUR) < NSTAGES) {                                             \
            const int par = (SCUR) & 1;                                     \
            if (half == 0) { if (lane == 31) sAy[par][colIdx] = Y[1]; }     \
            else           { if (lane == 0)  sBx[par][colIdx] = X[0]; }     \
            float xnr = __shfl_down_sync(0xFFFFFFFFu, X[0].x, 1);           \
            float xni = __shfl_down_sync(0xFFFFFFFFu, X[0].y, 1);           \
            float ypr = __shfl_up_sync  (0xFFFFFFFFu, Y[1].x, 1);           \
            float ypi = __shfl_up_sync  (0xFFFFFFFFu, Y[1].y, 1);           \
            __syncthreads();                                                \
            /* internal coupling (Y[0], X[1]) */                            \
            {                                                               \
                float2 y0 = Y[0], x1 = X[1];                                \
                Y[0].x = CS * y0.x - CN * x1.y;                             \
                Y[0].y = CS * y0.y + CN * x1.x;                             \
                X[1].x = CS * x1.x - CN * y0.y;                             \
                X[1].y = CS * x1.y + CN * y0.x;                             \
            }                                                               \
            float2 nx0, ny1;                                                \
            if (lane < 31) {                                                \
                ny1.x = CS * Y[1].x - CN * xni;                             \
                ny1.y = CS * Y[1].y + CN * xnr;                             \
            } else if (half == 0) {    /* row 127 <-> row 128 */            \
                float2 bx = sBx[par][colIdx];                               \
                ny1.x = CS * Y[1].x - CN * bx.y;                            \
                ny1.y = CS * Y[1].y + CN * bx.x;                            \
            } else {                   /* global row N-1 */                 \
                ny1.x = THRU * Y[1].x;                                      \
                ny1.y = THRU * Y[1].y;                                      \
            }                                                               \
            if (lane > 0) {                                                 \
                nx0.x = CS * X[0].x - CN * ypi;                             \
                nx0.y = CS * X[0].y + CN * ypr;                             \
            } else if (half == 1) {    /* row 128 <-> row 127 */            \
                float2 ay = sAy[par][colIdx];                               \
                nx0.x = CS * X[0].x - CN * ay.y;                            \
                nx0.y = CS * X[0].y + CN * ay.x;                            \
            } else {                   /* global row 0 */                   \
                nx0.x = THRU * X[0].x;                                      \
                nx0.y = THRU * X[0].y;                                      \
            }                                                               \
            X[0] = nx0; Y[1] = ny1;                                         \
        }                                                                   \
    } while (0)

    #pragma unroll 1
    for (int s = 1; s <= NSTAGES; s += 4) {
        STEP(s + 0, P0);
        STEP(s + 1, P1);
        STEP(s + 2, P2);
        STEP(s + 3, P3);
    }

    // P0 holds layer 129 (refilled at s=125). Store REAL PART, row-major.
    #pragma unroll
    for (int j = 0; j < 2; j++) {
        float4 p = P0[j];
        float xr = p.x * X[j].x - p.y * X[j].y;   // Re(p0 * x)
        float yr = p.z * Y[j].x - p.w * Y[j].y;   // Re(p1 * y)
        int r0 = 128 * half + 4 * lane + 2 * j;
        out[r0 * N + col]       = xr;
        out[(r0 + 1) * N + col] = yr;
    }
}

extern "C" void kernel_launch(void* const* d_in, const int* in_sizes, int n_in,
                              void* d_out, int out_size) {
    const float* thetas = (const float*)d_in[0];
    int n = in_sizes[0];  // 130 * 256 = 33280

    phase_kernel<<<(n + 255) / 256, 256>>>(thetas, n);
    // 128 CTAs x 128 threads = 512 warps; 4 warps/CTA -> 1 per SMSP,
    // 1 CTA/SM; each warp evolves a half-column.
    mesh_kernel<<<N / 2, 128>>>((float*)d_out);
}